// round 3
// baseline (speedup 1.0000x reference)
#include <cuda_runtime.h>
#include <math.h>

#define NB   32      // batch
#define PP   196     // pixels
#define ENC  2048
#define DECD 512
#define ATT  512
#define EMB  256
#define NV   30000
#define LL   21
#define NT   20      // decode steps
#define XK   (EMB + ENC)   // 2304

typedef unsigned long long u64;

// ---------- packed f32x2 helpers (sm_103a) ----------
__device__ __forceinline__ u64 pack2(float lo, float hi) {
    u64 r; asm("mov.b64 %0, {%1, %2};" : "=l"(r) : "f"(lo), "f"(hi)); return r;
}
__device__ __forceinline__ void unpack2(u64 v, float& lo, float& hi) {
    asm("mov.b64 {%0, %1}, %2;" : "=f"(lo), "=f"(hi) : "l"(v));
}
__device__ __forceinline__ u64 ffma2(u64 a, u64 b, u64 c) {
    u64 d; asm("fma.rn.f32x2 %0, %1, %2, %3;" : "=l"(d) : "l"(a), "l"(b), "l"(c)); return d;
}
__device__ __forceinline__ u64 fadd2(u64 a, u64 b) {
    u64 d; asm("add.rn.f32x2 %0, %1, %2;" : "=l"(d) : "l"(a), "l"(b)); return d;
}
__device__ __forceinline__ u64 warp_red2(u64 v) {
    #pragma unroll
    for (int o = 16; o > 0; o >>= 1)
        v = fadd2(v, __shfl_xor_sync(0xffffffffu, v, o));
    return v;
}

// ---------- persistent scratch (no cudaMalloc allowed) ----------
// Packed pair-major activations: layout [pair][k], element = (x[2p][k], x[2p+1][k])
__device__ __align__(16) float g_att1  [NB * PP * ATT];     // 12.8 MB (plain)
__device__ __align__(16) u64   g_meanpk[16 * ENC];
__device__ __align__(16) u64   g_hpk   [16 * DECD];
__device__ __align__(16) u64   g_cpk   [16 * DECD];
__device__ __align__(16) u64   g_att2pk[16 * ATT];
__device__ __align__(16) u64   g_xpk   [16 * XK];
__device__ __align__(16) u64   g_gpk   [16 * 4 * DECD];
__device__ __align__(16) float g_alpha [NB * PP];

// ============================================================
// mean over P (packed output)
// ============================================================
__global__ void mean_kernel(const float* __restrict__ enc, u64* __restrict__ meanpk)
{
    int b = blockIdx.x;
    for (int k = threadIdx.x; k < ENC; k += 256) {
        const float* p0 = enc + (size_t)b * PP * ENC + k;
        float s = 0.f;
        #pragma unroll 4
        for (int p = 0; p < PP; p++) s += p0[(size_t)p * ENC];
        ((unsigned*)meanpk)[(((size_t)(b >> 1)) * ENC + k) * 2 + (b & 1)] =
            __float_as_uint(s * (1.0f / PP));
    }
}

// ============================================================
// att1 GEMM: C[6272,512] = A[6272,2048] @ W[512,2048]^T + bias
// 128x64 tile, BK=32, software-pipelined global loads
// ============================================================
__global__ __launch_bounds__(256) void att1_gemm_kernel(
    const float* __restrict__ A, const float* __restrict__ W,
    const float* __restrict__ bias, float* __restrict__ C)
{
    __shared__ __align__(16) float As[32][128];
    __shared__ __align__(16) float Bs[32][64];
    const int tid = threadIdx.x;
    const int m0  = blockIdx.y * 128;
    const int n0  = blockIdx.x * 64;
    const int tmb = (tid & 15) * 2;
    const int tn  = (tid >> 4) * 4;

    u64 acc[4][4];
    #pragma unroll
    for (int i = 0; i < 4; i++)
        #pragma unroll
        for (int j = 0; j < 4; j++) acc[i][j] = 0ull;

    float4 av[4], bv[2];
    // prologue loads for k0 = 0
    #pragma unroll
    for (int r = 0; r < 4; r++) {
        int f = tid + r * 256; int m = f >> 3; int c = f & 7;
        av[r] = *(const float4*)(A + (size_t)(m0 + m) * ENC + c * 4);
    }
    #pragma unroll
    for (int r = 0; r < 2; r++) {
        int f = tid + r * 256; int n = f >> 3; int c = f & 7;
        bv[r] = *(const float4*)(W + (size_t)(n0 + n) * ENC + c * 4);
    }

    #pragma unroll 1
    for (int k0 = 0; k0 < ENC; k0 += 32) {
        __syncthreads();   // previous tile's compute done
        #pragma unroll
        for (int r = 0; r < 4; r++) {
            int f = tid + r * 256; int m = f >> 3; int c = f & 7;
            As[c*4+0][m] = av[r].x; As[c*4+1][m] = av[r].y;
            As[c*4+2][m] = av[r].z; As[c*4+3][m] = av[r].w;
        }
        #pragma unroll
        for (int r = 0; r < 2; r++) {
            int f = tid + r * 256; int n = f >> 3; int c = f & 7;
            Bs[c*4+0][n] = bv[r].x; Bs[c*4+1][n] = bv[r].y;
            Bs[c*4+2][n] = bv[r].z; Bs[c*4+3][n] = bv[r].w;
        }
        __syncthreads();
        // prefetch next tile while computing this one (av/bv dead after staging)
        if (k0 + 32 < ENC) {
            #pragma unroll
            for (int r = 0; r < 4; r++) {
                int f = tid + r * 256; int m = f >> 3; int c = f & 7;
                av[r] = *(const float4*)(A + (size_t)(m0 + m) * ENC + k0 + 32 + c * 4);
            }
            #pragma unroll
            for (int r = 0; r < 2; r++) {
                int f = tid + r * 256; int n = f >> 3; int c = f & 7;
                bv[r] = *(const float4*)(W + (size_t)(n0 + n) * ENC + k0 + 32 + c * 4);
            }
        }
        #pragma unroll 8
        for (int k = 0; k < 32; k++) {
            u64 a2[4];
            #pragma unroll
            for (int i = 0; i < 4; i++)
                a2[i] = *(const u64*)&As[k][tmb + 32 * i];
            float4 b4 = *(const float4*)&Bs[k][tn];
            u64 bd[4] = { pack2(b4.x, b4.x), pack2(b4.y, b4.y),
                          pack2(b4.z, b4.z), pack2(b4.w, b4.w) };
            #pragma unroll
            for (int i = 0; i < 4; i++)
                #pragma unroll
                for (int j = 0; j < 4; j++)
                    acc[i][j] = ffma2(a2[i], bd[j], acc[i][j]);
        }
    }
    #pragma unroll
    for (int i = 0; i < 4; i++) {
        int m = m0 + tmb + 32 * i;
        #pragma unroll
        for (int j = 0; j < 4; j++) {
            int n = n0 + tn + j;
            float lo, hi; unpack2(acc[i][j], lo, hi);
            float bb = bias[n];
            C[(size_t)m       * ATT + n] = lo + bb;
            C[(size_t)(m + 1) * ATT + n] = hi + bb;
        }
    }
}

// ============================================================
// Skinny GEMM v3: out[b][n] = b1[n](+b2[n]) + A1pk[b]·W1[n] (+ A2pk[b]·W2[n])
// A in packed pair-major layout. Pure-register kernel: no smem, no syncs.
// Each block: ntiles tiles of 16 n, all 32 batches, full K.
// Warp layout: ng = w&1 (8-n half), bg = w>>1 (4 batch-pairs).
// Lane covers k = k0 + 2*lane, k0+2*lane+1 within each 64-k chunk.
// K must be a multiple of 64.
// ============================================================
__global__ __launch_bounds__(256, 2) void skinny3_kernel(
    const u64* __restrict__ A1, const float* __restrict__ W1, int K1,
    const u64* __restrict__ A2, const float* __restrict__ W2, int K2,
    const float* __restrict__ b1, const float* __restrict__ b2,
    float* __restrict__ out, int ldc,      // plain-out mode (if out != null)
    u64* __restrict__ outp, int ldn,       // packed-out mode
    int Ntot, int ntiles)
{
    const int tid  = threadIdx.x;
    const int lane = tid & 31;
    const int w    = tid >> 5;
    const int ng   = w & 1;
    const int bg   = w >> 1;          // 0..3 -> pairs bg*4 .. bg*4+3
    const int kl   = 2 * lane;

    for (int t = 0; t < ntiles; t++) {
        const int nbase = (blockIdx.x * ntiles + t) * 16 + ng * 8;
        int nc[8];
        #pragma unroll
        for (int j = 0; j < 8; j++) {
            int n = nbase + j;
            nc[j] = (n < Ntot) ? n : (Ntot - 1);
        }

        u64 acc[4][8];
        #pragma unroll
        for (int i = 0; i < 4; i++)
            #pragma unroll
            for (int j = 0; j < 8; j++) acc[i][j] = 0ull;

        #pragma unroll 1
        for (int seg = 0; seg < 2; seg++) {
            const u64*   A = seg ? A2 : A1;
            const float* W = seg ? W2 : W1;
            const int    K = seg ? K2 : K1;
            if (A == nullptr) continue;

            float2 wv[8];
            #pragma unroll
            for (int j = 0; j < 8; j++)
                wv[j] = *(const float2*)(W + (size_t)nc[j] * K + kl);

            #pragma unroll 1
            for (int k0 = 0; k0 < K; k0 += 64) {
                u64 wdx[8], wdy[8];
                #pragma unroll
                for (int j = 0; j < 8; j++) {
                    wdx[j] = pack2(wv[j].x, wv[j].x);
                    wdy[j] = pack2(wv[j].y, wv[j].y);
                }
                // prefetch next chunk's W while ffma2 block runs
                if (k0 + 64 < K) {
                    #pragma unroll
                    for (int j = 0; j < 8; j++)
                        wv[j] = *(const float2*)(W + (size_t)nc[j] * K + k0 + 64 + kl);
                }
                #pragma unroll
                for (int i = 0; i < 4; i++) {
                    const int pi = bg * 4 + i;
                    ulonglong2 xx = *(const ulonglong2*)(A + (size_t)pi * K + k0 + kl);
                    #pragma unroll
                    for (int j = 0; j < 8; j++) {
                        acc[i][j] = ffma2(xx.x, wdx[j], acc[i][j]);
                        acc[i][j] = ffma2(xx.y, wdy[j], acc[i][j]);
                    }
                }
            }
        }

        // cross-lane reduce (lanes hold disjoint k) and write
        #pragma unroll
        for (int i = 0; i < 4; i++)
            #pragma unroll
            for (int j = 0; j < 8; j++) acc[i][j] = warp_red2(acc[i][j]);

        if (lane == 0) {
            #pragma unroll
            for (int i = 0; i < 4; i++) {
                const int pi = bg * 4 + i;
                #pragma unroll
                for (int j = 0; j < 8; j++) {
                    int n = nbase + j;
                    if (n >= Ntot) continue;
                    float bb = b1[n] + (b2 ? b2[n] : 0.0f);
                    if (outp) {
                        outp[(size_t)pi * ldn + n] = fadd2(acc[i][j], pack2(bb, bb));
                    } else {
                        float lo, hi; unpack2(acc[i][j], lo, hi);
                        out[(size_t)(2 * pi)     * ldc + n] = lo + bb;
                        out[(size_t)(2 * pi + 1) * ldc + n] = hi + bb;
                    }
                }
            }
        }
    }
}

// ============================================================
// Fused attention: escore + softmax + alpha writes + embedding gather.
// One block per batch element.
// ============================================================
__global__ void att_fused_kernel(const float* __restrict__ att1,
                                 const u64* __restrict__ att2pk,
                                 const float* __restrict__ Wf,
                                 const float* __restrict__ bf,
                                 float* __restrict__ alpha,
                                 float* __restrict__ out_alpha, int t,
                                 const int* __restrict__ captions,
                                 const float* __restrict__ emb,
                                 u64* __restrict__ xpk)
{
    __shared__ __align__(16) float sA[ATT];
    __shared__ __align__(16) float sW[ATT];
    __shared__ float sE[256];
    __shared__ float red[256];
    __shared__ int s_idx;

    const int b = blockIdx.x, tid = threadIdx.x;
    const int half = b & 1, pair = b >> 1;

    for (int a = tid; a < ATT; a += 256) {
        sA[a] = ((const float*)&att2pk[(size_t)pair * ATT + a])[half];
        sW[a] = Wf[a];
    }
    sE[tid] = -3.4e38f;
    __syncthreads();

    const int w = tid >> 5, lane = tid & 31;
    for (int p = w; p < PP; p += 8) {
        const float4* row = (const float4*)(att1 + ((size_t)b * PP + p) * ATT);
        const float4* a4  = (const float4*)sA;
        const float4* w4  = (const float4*)sW;
        float acc = 0.f;
        #pragma unroll
        for (int c = lane; c < ATT / 4; c += 32) {
            float4 v = row[c], h = a4[c], f = w4[c];
            acc += fmaxf(v.x + h.x, 0.f) * f.x + fmaxf(v.y + h.y, 0.f) * f.y
                 + fmaxf(v.z + h.z, 0.f) * f.z + fmaxf(v.w + h.w, 0.f) * f.w;
        }
        #pragma unroll
        for (int o = 16; o > 0; o >>= 1) acc += __shfl_xor_sync(0xffffffffu, acc, o);
        if (lane == 0) sE[p] = acc + bf[0];
    }
    __syncthreads();

    // softmax over sE[0..195]
    float v = sE[tid];
    red[tid] = v; __syncthreads();
    #pragma unroll
    for (int s = 128; s > 0; s >>= 1) {
        if (tid < s) red[tid] = fmaxf(red[tid], red[tid + s]);
        __syncthreads();
    }
    float mx = red[0]; __syncthreads();
    float ex = (tid < PP) ? expf(v - mx) : 0.f;
    red[tid] = ex; __syncthreads();
    #pragma unroll
    for (int s = 128; s > 0; s >>= 1) {
        if (tid < s) red[tid] += red[tid + s];
        __syncthreads();
    }
    float inv = 1.0f / red[0];
    if (tid < PP) {
        float a = ex * inv;
        alpha[b * PP + tid] = a;
        out_alpha[(size_t)(b * NT + t) * PP + tid] = a;
    }

    if (tid == 0) {
        // dtype hedge: int64 captions -> every odd 32-bit word is 0
        bool is64 = true;
        #pragma unroll
        for (int i = 0; i < 32; i++)
            if (captions[2 * i + 1] != 0) is64 = false;
        int pos = b * LL + t;
        s_idx = is64 ? captions[2 * pos] : captions[pos];
    }
    __syncthreads();
    // embedding -> packed x buffer (256 threads == EMB)
    ((unsigned*)xpk)[(((size_t)pair) * XK + tid) * 2 + half] =
        __float_as_uint(emb[(size_t)s_idx * EMB + tid]);
}

// ============================================================
// awe[b][k] = sum_p alpha[b,p] * enc[b,p,k]  -> packed x buffer at +EMB
// ============================================================
__global__ void awe_kernel(const float* __restrict__ enc,
                           const float* __restrict__ alpha,
                           u64* __restrict__ xpk)
{
    __shared__ float al[PP];
    int b = blockIdx.y;
    int k = blockIdx.x * 256 + threadIdx.x;
    if (threadIdx.x < PP) al[threadIdx.x] = alpha[b * PP + threadIdx.x];
    __syncthreads();
    const float* ep = enc + (size_t)b * PP * ENC + k;
    float acc = 0.f;
    #pragma unroll 4
    for (int p = 0; p < PP; p++) acc += al[p] * ep[(size_t)p * ENC];
    ((unsigned*)xpk)[(((size_t)(b >> 1)) * XK + EMB + k) * 2 + (b & 1)] =
        __float_as_uint(acc);
}

// ============================================================
// LSTM pointwise on batch pairs (PyTorch gate order i,f,g,o)
// ============================================================
__global__ void lstm_pair_kernel(const u64* __restrict__ gpk,
                                 u64* __restrict__ hpk, u64* __restrict__ cpk)
{
    int idx  = blockIdx.x * 256 + threadIdx.x;  // 16 pairs * 512 j
    int pair = idx >> 9, j = idx & 511;
    const u64* g = gpk + (size_t)pair * 4 * DECD;
    float i0, i1, f0, f1, g0, g1, o0, o1, c0, c1;
    unpack2(g[j],            i0, i1);
    unpack2(g[j + DECD],     f0, f1);
    unpack2(g[j + 2 * DECD], g0, g1);
    unpack2(g[j + 3 * DECD], o0, o1);
    unpack2(cpk[(size_t)pair * DECD + j], c0, c1);
    float si0 = 1.f / (1.f + expf(-i0)), si1 = 1.f / (1.f + expf(-i1));
    float sf0 = 1.f / (1.f + expf(-f0)), sf1 = 1.f / (1.f + expf(-f1));
    float so0 = 1.f / (1.f + expf(-o0)), so1 = 1.f / (1.f + expf(-o1));
    float cn0 = sf0 * c0 + si0 * tanhf(g0);
    float cn1 = sf1 * c1 + si1 * tanhf(g1);
    float hn0 = so0 * tanhf(cn0);
    float hn1 = so1 * tanhf(cn1);
    cpk[(size_t)pair * DECD + j] = pack2(cn0, cn1);
    hpk[(size_t)pair * DECD + j] = pack2(hn0, hn1);
}

// ============================================================
extern "C" void kernel_launch(void* const* d_in, const int* in_sizes, int n_in,
                              void* d_out, int out_size)
{
    const float* enc  = (const float*)d_in[0];
    const int*   caps = (const int*)  d_in[1];
    const float* emb  = (const float*)d_in[3];
    const float* We   = (const float*)d_in[4];
    const float* be   = (const float*)d_in[5];
    const float* Wd   = (const float*)d_in[6];
    const float* bd   = (const float*)d_in[7];
    const float* Wf   = (const float*)d_in[8];
    const float* bf   = (const float*)d_in[9];
    const float* Wih  = (const float*)d_in[10];
    const float* bih  = (const float*)d_in[11];
    const float* Whh  = (const float*)d_in[12];
    const float* bhh  = (const float*)d_in[13];
    const float* Wfc  = (const float*)d_in[14];
    const float* bfc  = (const float*)d_in[15];
    const float* Wh0  = (const float*)d_in[16];
    const float* bh0  = (const float*)d_in[17];
    const float* Wc0  = (const float*)d_in[18];
    const float* bc0  = (const float*)d_in[19];

    float* out       = (float*)d_out;                  // predictions [32,20,30000]
    float* out_alpha = out + (size_t)NB * NT * NV;     // alphas      [32,20,196]

    float *p_att1, *p_alpha;
    u64 *p_meanpk, *p_hpk, *p_cpk, *p_att2pk, *p_xpk, *p_gpk;
    cudaGetSymbolAddress((void**)&p_att1,   g_att1);
    cudaGetSymbolAddress((void**)&p_alpha,  g_alpha);
    cudaGetSymbolAddress((void**)&p_meanpk, g_meanpk);
    cudaGetSymbolAddress((void**)&p_hpk,    g_hpk);
    cudaGetSymbolAddress((void**)&p_cpk,    g_cpk);
    cudaGetSymbolAddress((void**)&p_att2pk, g_att2pk);
    cudaGetSymbolAddress((void**)&p_xpk,    g_xpk);
    cudaGetSymbolAddress((void**)&p_gpk,    g_gpk);

    // ---- init ----
    mean_kernel<<<NB, 256>>>(enc, p_meanpk);
    skinny3_kernel<<<DECD / 16, 256>>>(p_meanpk, Wh0, ENC, nullptr, nullptr, 0,
                                       bh0, nullptr, nullptr, 0, p_hpk, DECD, DECD, 1);
    skinny3_kernel<<<DECD / 16, 256>>>(p_meanpk, Wc0, ENC, nullptr, nullptr, 0,
                                       bc0, nullptr, nullptr, 0, p_cpk, DECD, DECD, 1);
    att1_gemm_kernel<<<dim3(ATT / 64, (NB * PP) / 128), 256>>>(enc, We, be, p_att1);

    // ---- decode loop ----
    const int preds_ntiles = 4;
    const int preds_blocks = (NV + 16 * preds_ntiles - 1) / (16 * preds_ntiles); // 469
    for (int t = 0; t < NT; t++) {
        skinny3_kernel<<<ATT / 16, 256>>>(p_hpk, Wd, DECD, nullptr, nullptr, 0,
                                          bd, nullptr, nullptr, 0, p_att2pk, ATT, ATT, 1);
        att_fused_kernel<<<NB, 256>>>(p_att1, p_att2pk, Wf, bf, p_alpha,
                                      out_alpha, t, caps, emb, p_xpk);
        awe_kernel<<<dim3(ENC / 256, NB), 256>>>(enc, p_alpha, p_xpk);
        skinny3_kernel<<<(4 * DECD) / 16, 256>>>(p_xpk, Wih, XK, p_hpk, Whh, DECD,
                                                 bih, bhh, nullptr, 0,
                                                 p_gpk, 4 * DECD, 4 * DECD, 1);
        lstm_pair_kernel<<<(16 * DECD) / 256, 256>>>(p_gpk, p_hpk, p_cpk);
        skinny3_kernel<<<preds_blocks, 256>>>(p_hpk, Wfc, DECD, nullptr, nullptr, 0,
                                              bfc, nullptr, out + (size_t)t * NV, NT * NV,
                                              nullptr, 0, NV, preds_ntiles);
    }
}

// round 4
// speedup vs baseline: 1.6870x; 1.6870x over previous
#include <cuda_runtime.h>
#include <math.h>

#define NB   32      // batch
#define PP   196     // pixels
#define ENC  2048
#define DECD 512
#define ATT  512
#define EMB  256
#define NV   30000
#define LL   21
#define NT   20      // decode steps
#define XK   (EMB + ENC)   // 2304

typedef unsigned long long u64;

// ---------- packed f32x2 helpers (sm_103a) ----------
__device__ __forceinline__ u64 pack2(float lo, float hi) {
    u64 r; asm("mov.b64 %0, {%1, %2};" : "=l"(r) : "f"(lo), "f"(hi)); return r;
}
__device__ __forceinline__ void unpack2(u64 v, float& lo, float& hi) {
    asm("mov.b64 {%0, %1}, %2;" : "=f"(lo), "=f"(hi) : "l"(v));
}
__device__ __forceinline__ u64 ffma2(u64 a, u64 b, u64 c) {
    u64 d; asm("fma.rn.f32x2 %0, %1, %2, %3;" : "=l"(d) : "l"(a), "l"(b), "l"(c)); return d;
}
__device__ __forceinline__ u64 fadd2(u64 a, u64 b) {
    u64 d; asm("add.rn.f32x2 %0, %1, %2;" : "=l"(d) : "l"(a), "l"(b)); return d;
}

// ---------- persistent scratch (no cudaMalloc allowed) ----------
__device__ __align__(16) float g_att1 [NB * PP * ATT];     // 12.8 MB
__device__ __align__(16) float g_mean [NB * ENC];
__device__ __align__(16) float g_h    [NB * DECD];
__device__ __align__(16) float g_c    [NB * DECD];
__device__ __align__(16) float g_att2 [NB * ATT];
__device__ __align__(16) float g_alpha[NB * PP];
__device__ __align__(16) float g_x    [NB * XK];
__device__ __align__(16) float g_gates[NB * 4 * DECD];
__device__ __align__(16) float g_hall [NT * NB * DECD];    // all h_t, rows m = t*32+b

// ============================================================
// mean over P
// ============================================================
__global__ void mean_kernel(const float* __restrict__ enc, float* __restrict__ mean)
{
    int b = blockIdx.x;
    for (int k = threadIdx.x; k < ENC; k += 256) {
        const float* p0 = enc + (size_t)b * PP * ENC + k;
        float s = 0.f;
        #pragma unroll 4
        for (int p = 0; p < PP; p++) s += p0[(size_t)p * ENC];
        mean[b * ENC + k] = s * (1.0f / PP);
    }
}

// ============================================================
// Big tiled GEMM: C[M,Ntot] = A[M,K] @ W[Ntot,K]^T + bias
// 128x64 tile, BK=32, software-pipelined, f32x2 accumulators.
// remap=0: C[m*ldc + n].  remap=1 (preds): row m = t*32+b -> out[(b*NT+t)*Ntot + n].
// M must be a multiple of 128, K a multiple of 32. N edge guarded.
// ============================================================
__global__ __launch_bounds__(256, 3) void gemm_kernel(
    const float* __restrict__ A, const float* __restrict__ W,
    const float* __restrict__ bias, float* __restrict__ C,
    int K, int Ntot, int ldc, int remap)
{
    __shared__ __align__(16) float As[32][128];
    __shared__ __align__(16) float Bs[32][64];
    const int tid = threadIdx.x;
    const int m0  = blockIdx.y * 128;
    const int n0  = blockIdx.x * 64;
    const int tmb = (tid & 15) * 2;
    const int tn  = (tid >> 4) * 4;

    u64 acc[4][4];
    #pragma unroll
    for (int i = 0; i < 4; i++)
        #pragma unroll
        for (int j = 0; j < 4; j++) acc[i][j] = 0ull;

    float4 av[4], bv[2];
    #pragma unroll
    for (int r = 0; r < 4; r++) {
        int f = tid + r * 256; int m = f >> 3; int c = f & 7;
        av[r] = *(const float4*)(A + (size_t)(m0 + m) * K + c * 4);
    }
    #pragma unroll
    for (int r = 0; r < 2; r++) {
        int f = tid + r * 256; int n = n0 + (f >> 3); int c = f & 7;
        if (n >= Ntot) n = Ntot - 1;
        bv[r] = *(const float4*)(W + (size_t)n * K + c * 4);
    }

    #pragma unroll 1
    for (int k0 = 0; k0 < K; k0 += 32) {
        __syncthreads();
        #pragma unroll
        for (int r = 0; r < 4; r++) {
            int f = tid + r * 256; int m = f >> 3; int c = f & 7;
            As[c*4+0][m] = av[r].x; As[c*4+1][m] = av[r].y;
            As[c*4+2][m] = av[r].z; As[c*4+3][m] = av[r].w;
        }
        #pragma unroll
        for (int r = 0; r < 2; r++) {
            int f = tid + r * 256; int n = f >> 3; int c = f & 7;
            Bs[c*4+0][n] = bv[r].x; Bs[c*4+1][n] = bv[r].y;
            Bs[c*4+2][n] = bv[r].z; Bs[c*4+3][n] = bv[r].w;
        }
        __syncthreads();
        if (k0 + 32 < K) {
            #pragma unroll
            for (int r = 0; r < 4; r++) {
                int f = tid + r * 256; int m = f >> 3; int c = f & 7;
                av[r] = *(const float4*)(A + (size_t)(m0 + m) * K + k0 + 32 + c * 4);
            }
            #pragma unroll
            for (int r = 0; r < 2; r++) {
                int f = tid + r * 256; int n = n0 + (f >> 3); int c = f & 7;
                if (n >= Ntot) n = Ntot - 1;
                bv[r] = *(const float4*)(W + (size_t)n * K + k0 + 32 + c * 4);
            }
        }
        #pragma unroll 8
        for (int k = 0; k < 32; k++) {
            u64 a2[4];
            #pragma unroll
            for (int i = 0; i < 4; i++)
                a2[i] = *(const u64*)&As[k][tmb + 32 * i];
            float4 b4 = *(const float4*)&Bs[k][tn];
            u64 bd[4] = { pack2(b4.x, b4.x), pack2(b4.y, b4.y),
                          pack2(b4.z, b4.z), pack2(b4.w, b4.w) };
            #pragma unroll
            for (int i = 0; i < 4; i++)
                #pragma unroll
                for (int j = 0; j < 4; j++)
                    acc[i][j] = ffma2(a2[i], bd[j], acc[i][j]);
        }
    }
    #pragma unroll
    for (int i = 0; i < 4; i++) {
        int m = m0 + tmb + 32 * i;
        #pragma unroll
        for (int j = 0; j < 4; j++) {
            int n = n0 + tn + j;
            if (n >= Ntot) continue;
            float lo, hi; unpack2(acc[i][j], lo, hi);
            float bb = bias[n];
            if (remap) {
                int t0 = m >> 5,  b0 = m & 31;
                int t1 = (m + 1) >> 5, b1 = (m + 1) & 31;
                C[(size_t)(b0 * NT + t0) * Ntot + n] = lo + bb;
                C[(size_t)(b1 * NT + t1) * Ntot + n] = hi + bb;
            } else {
                C[(size_t)m       * ldc + n] = lo + bb;
                C[(size_t)(m + 1) * ldc + n] = hi + bb;
            }
        }
    }
}

// ============================================================
// Skinny GEMM (round-2 proven): out[b][n] = b1[n](+b2[n]) + A1[b]·W1[n] (+A2[b]·W2[n])
// 32 batch rows x 16 n per block; batch packed in pairs (f32x2). K % 64 == 0.
// ============================================================
__global__ __launch_bounds__(256) void skinny_gemm_kernel(
    const float* __restrict__ A1, const float* __restrict__ W1, int K1,
    const float* __restrict__ A2, const float* __restrict__ W2, int K2,
    const float* __restrict__ bias1, const float* __restrict__ bias2,
    float* __restrict__ out, int ldc)
{
    __shared__ __align__(16) u64 xs[16][64];
    const int tid  = threadIdx.x;
    const int lane = tid & 31;
    const int w    = tid >> 5;
    const int ng   = w & 3;
    const int bg   = w >> 2;
    const int n0   = blockIdx.x * 16 + ng * 4;
    const int b2s  = tid >> 4;
    const int c4   = tid & 15;

    u64 acc[8][4];
    #pragma unroll
    for (int i = 0; i < 8; i++)
        #pragma unroll
        for (int j = 0; j < 4; j++) acc[i][j] = 0ull;

    #pragma unroll 1
    for (int seg = 0; seg < 2; seg++) {
        const float* A = seg ? A2 : A1;
        const float* W = seg ? W2 : W1;
        const int    K = seg ? K2 : K1;
        if (A == nullptr) continue;
        for (int k0 = 0; k0 < K; k0 += 64) {
            float4 lo4 = *(const float4*)(A + (size_t)(2 * b2s)     * K + k0 + c4 * 4);
            float4 hi4 = *(const float4*)(A + (size_t)(2 * b2s + 1) * K + k0 + c4 * 4);
            __syncthreads();
            xs[b2s][c4*4+0] = pack2(lo4.x, hi4.x);
            xs[b2s][c4*4+1] = pack2(lo4.y, hi4.y);
            xs[b2s][c4*4+2] = pack2(lo4.z, hi4.z);
            xs[b2s][c4*4+3] = pack2(lo4.w, hi4.w);
            __syncthreads();
            const float* wp = W + k0 + lane;
            u64 wd0[4], wd1[4];
            #pragma unroll
            for (int j = 0; j < 4; j++) {
                const float* r = wp + (size_t)(n0 + j) * K;
                float w0 = r[0], w1 = r[32];
                wd0[j] = pack2(w0, w0);
                wd1[j] = pack2(w1, w1);
            }
            #pragma unroll
            for (int i = 0; i < 8; i++) {
                u64 x0 = xs[bg * 8 + i][lane];
                u64 x1 = xs[bg * 8 + i][lane + 32];
                #pragma unroll
                for (int j = 0; j < 4; j++) {
                    acc[i][j] = ffma2(x0, wd0[j], acc[i][j]);
                    acc[i][j] = ffma2(x1, wd1[j], acc[i][j]);
                }
            }
        }
    }
    #pragma unroll
    for (int i = 0; i < 8; i++)
        #pragma unroll
        for (int j = 0; j < 4; j++) {
            u64 v = acc[i][j];
            #pragma unroll
            for (int o = 16; o > 0; o >>= 1)
                v = fadd2(v, __shfl_xor_sync(0xffffffffu, v, o));
            acc[i][j] = v;
        }
    if (lane == 0) {
        #pragma unroll
        for (int i = 0; i < 8; i++) {
            int b = (bg * 8 + i) * 2;
            #pragma unroll
            for (int j = 0; j < 4; j++) {
                int n = n0 + j;
                float bb = bias1[n] + (bias2 ? bias2[n] : 0.0f);
                float lo, hi; unpack2(acc[i][j], lo, hi);
                out[(size_t)b       * ldc + n] = lo + bb;
                out[(size_t)(b + 1) * ldc + n] = hi + bb;
            }
        }
    }
}

// ============================================================
// Fused attention: escore + softmax + alpha writes + embedding gather.
// One block per batch element.
// ============================================================
__global__ void att_fused_kernel(const float* __restrict__ att1,
                                 const float* __restrict__ att2,
                                 const float* __restrict__ Wf,
                                 const float* __restrict__ bf,
                                 float* __restrict__ alpha,
                                 float* __restrict__ out_alpha, int t,
                                 const int* __restrict__ captions,
                                 const float* __restrict__ emb,
                                 float* __restrict__ xbuf)
{
    __shared__ __align__(16) float sA[ATT];
    __shared__ __align__(16) float sW[ATT];
    __shared__ float sE[256];
    __shared__ float red[256];
    __shared__ int s_idx;

    const int b = blockIdx.x, tid = threadIdx.x;

    for (int a = tid; a < ATT; a += 256) {
        sA[a] = att2[(size_t)b * ATT + a];
        sW[a] = Wf[a];
    }
    sE[tid] = -3.4e38f;
    __syncthreads();

    const int w = tid >> 5, lane = tid & 31;
    for (int p = w; p < PP; p += 8) {
        const float4* row = (const float4*)(att1 + ((size_t)b * PP + p) * ATT);
        const float4* a4  = (const float4*)sA;
        const float4* w4  = (const float4*)sW;
        float acc = 0.f;
        #pragma unroll
        for (int c = lane; c < ATT / 4; c += 32) {
            float4 v = row[c], h = a4[c], f = w4[c];
            acc += fmaxf(v.x + h.x, 0.f) * f.x + fmaxf(v.y + h.y, 0.f) * f.y
                 + fmaxf(v.z + h.z, 0.f) * f.z + fmaxf(v.w + h.w, 0.f) * f.w;
        }
        #pragma unroll
        for (int o = 16; o > 0; o >>= 1) acc += __shfl_xor_sync(0xffffffffu, acc, o);
        if (lane == 0) sE[p] = acc + bf[0];
    }
    __syncthreads();

    float v = sE[tid];
    red[tid] = v; __syncthreads();
    #pragma unroll
    for (int s = 128; s > 0; s >>= 1) {
        if (tid < s) red[tid] = fmaxf(red[tid], red[tid + s]);
        __syncthreads();
    }
    float mx = red[0]; __syncthreads();
    float ex = (tid < PP) ? expf(v - mx) : 0.f;
    red[tid] = ex; __syncthreads();
    #pragma unroll
    for (int s = 128; s > 0; s >>= 1) {
        if (tid < s) red[tid] += red[tid + s];
        __syncthreads();
    }
    float inv = 1.0f / red[0];
    if (tid < PP) {
        float a = ex * inv;
        alpha[b * PP + tid] = a;
        out_alpha[(size_t)(b * NT + t) * PP + tid] = a;
    }

    if (tid == 0) {
        // dtype hedge: int64 captions -> every odd 32-bit word is 0
        bool is64 = true;
        #pragma unroll
        for (int i = 0; i < 32; i++)
            if (captions[2 * i + 1] != 0) is64 = false;
        int pos = b * LL + t;
        s_idx = is64 ? captions[2 * pos] : captions[pos];
    }
    __syncthreads();
    xbuf[(size_t)b * XK + tid] = emb[(size_t)s_idx * EMB + tid];  // 256 threads == EMB
}

// ============================================================
// awe[b][k] = sum_p alpha[b,p] * enc[b,p,k]  -> x buffer at +EMB
// ============================================================
__global__ void awe_kernel(const float* __restrict__ enc,
                           const float* __restrict__ alpha,
                           float* __restrict__ xbuf)
{
    __shared__ float al[PP];
    int b = blockIdx.y;
    int k = blockIdx.x * 256 + threadIdx.x;
    if (threadIdx.x < PP) al[threadIdx.x] = alpha[b * PP + threadIdx.x];
    __syncthreads();
    const float* ep = enc + (size_t)b * PP * ENC + k;
    float acc = 0.f;
    #pragma unroll 4
    for (int p = 0; p < PP; p++) acc += al[p] * ep[(size_t)p * ENC];
    xbuf[(size_t)b * XK + EMB + k] = acc;
}

// ============================================================
// LSTM pointwise (PyTorch gate order i,f,g,o); also records h_t into Hall
// ============================================================
__global__ void lstm_kernel(const float* __restrict__ gates,
                            float* __restrict__ h, float* __restrict__ c,
                            float* __restrict__ hall, int t)
{
    int i = blockIdx.x * 256 + threadIdx.x;   // 32*512
    int b = i >> 9, j = i & 511;
    const float* g = gates + (size_t)b * 4 * DECD;
    float ig = g[j], fg = g[DECD + j], gg = g[2 * DECD + j], og = g[3 * DECD + j];
    float si = 1.f / (1.f + expf(-ig));
    float sf = 1.f / (1.f + expf(-fg));
    float so = 1.f / (1.f + expf(-og));
    float cn = sf * c[i] + si * tanhf(gg);
    float hn = so * tanhf(cn);
    c[i] = cn; h[i] = hn;
    hall[(size_t)(t * NB + b) * DECD + j] = hn;
}

// ============================================================
extern "C" void kernel_launch(void* const* d_in, const int* in_sizes, int n_in,
                              void* d_out, int out_size)
{
    const float* enc  = (const float*)d_in[0];
    const int*   caps = (const int*)  d_in[1];
    const float* emb  = (const float*)d_in[3];
    const float* We   = (const float*)d_in[4];
    const float* be   = (const float*)d_in[5];
    const float* Wd   = (const float*)d_in[6];
    const float* bd   = (const float*)d_in[7];
    const float* Wf   = (const float*)d_in[8];
    const float* bf   = (const float*)d_in[9];
    const float* Wih  = (const float*)d_in[10];
    const float* bih  = (const float*)d_in[11];
    const float* Whh  = (const float*)d_in[12];
    const float* bhh  = (const float*)d_in[13];
    const float* Wfc  = (const float*)d_in[14];
    const float* bfc  = (const float*)d_in[15];
    const float* Wh0  = (const float*)d_in[16];
    const float* bh0  = (const float*)d_in[17];
    const float* Wc0  = (const float*)d_in[18];
    const float* bc0  = (const float*)d_in[19];

    float* out       = (float*)d_out;                  // predictions [32,20,30000]
    float* out_alpha = out + (size_t)NB * NT * NV;     // alphas      [32,20,196]

    float *p_att1, *p_mean, *p_h, *p_c, *p_att2, *p_alpha, *p_x, *p_gates, *p_hall;
    cudaGetSymbolAddress((void**)&p_att1,  g_att1);
    cudaGetSymbolAddress((void**)&p_mean,  g_mean);
    cudaGetSymbolAddress((void**)&p_h,     g_h);
    cudaGetSymbolAddress((void**)&p_c,     g_c);
    cudaGetSymbolAddress((void**)&p_att2,  g_att2);
    cudaGetSymbolAddress((void**)&p_alpha, g_alpha);
    cudaGetSymbolAddress((void**)&p_x,     g_x);
    cudaGetSymbolAddress((void**)&p_gates, g_gates);
    cudaGetSymbolAddress((void**)&p_hall,  g_hall);

    // ---- init ----
    mean_kernel<<<NB, 256>>>(enc, p_mean);
    skinny_gemm_kernel<<<DECD / 16, 256>>>(p_mean, Wh0, ENC, nullptr, nullptr, 0,
                                           bh0, nullptr, p_h, DECD);
    skinny_gemm_kernel<<<DECD / 16, 256>>>(p_mean, Wc0, ENC, nullptr, nullptr, 0,
                                           bc0, nullptr, p_c, DECD);
    gemm_kernel<<<dim3(ATT / 64, (NB * PP) / 128), 256>>>(enc, We, be, p_att1,
                                                          ENC, ATT, ATT, 0);

    // ---- decode loop (preds hoisted out) ----
    for (int t = 0; t < NT; t++) {
        skinny_gemm_kernel<<<ATT / 16, 256>>>(p_h, Wd, DECD, nullptr, nullptr, 0,
                                              bd, nullptr, p_att2, ATT);
        att_fused_kernel<<<NB, 256>>>(p_att1, p_att2, Wf, bf, p_alpha,
                                      out_alpha, t, caps, emb, p_x);
        awe_kernel<<<dim3(ENC / 256, NB), 256>>>(enc, p_alpha, p_x);
        skinny_gemm_kernel<<<(4 * DECD) / 16, 256>>>(p_x, Wih, XK, p_h, Whh, DECD,
                                                     bih, bhh, p_gates, 4 * DECD);
        lstm_kernel<<<(NB * DECD) / 256, 256>>>(p_gates, p_h, p_c, p_hall, t);
    }

    // ---- batched predictions: [640,512] @ [512,30000]^T, rows remapped ----
    gemm_kernel<<<dim3((NV + 63) / 64, (NT * NB) / 128), 256>>>(
        p_hall, Wfc, bfc, out, DECD, NV, 0, 1);
}